// round 1
// baseline (speedup 1.0000x reference)
#include <cuda_runtime.h>

// Segment-sum: out[index[r], :] += src[r, :], src is (nrows, 64) fp32,
// out is (dim_size, 64) fp32. Single-pass scatter with vector L2 reductions.

__device__ int g_idx_is64;

// Detect whether the index buffer is int64 or int32 at runtime.
// Interpreting an int32 array (values in [0, 50000)) as int64 yields
// huge values (random high word) with overwhelming probability, so if all
// 16 sampled int64 values are in range, the buffer really is int64.
__global__ void detect_idx_width_kernel(const void* __restrict__ idx,
                                        long long dim_size) {
    if (blockIdx.x == 0 && threadIdx.x == 0) {
        const long long* p = (const long long*)idx;
        int is64 = 1;
        #pragma unroll
        for (int i = 0; i < 16; i++) {
            long long v = p[i];
            if (v < 0 || v >= dim_size) { is64 = 0; break; }
        }
        g_idx_is64 = is64;
    }
}

__global__ void zero_out_kernel(float4* __restrict__ out, int n4) {
    int i = blockIdx.x * blockDim.x + threadIdx.x;
    if (i < n4) out[i] = make_float4(0.f, 0.f, 0.f, 0.f);
}

// Each thread owns one 16-byte chunk of one source row:
//   t = row * 16 + c   (64 floats per row = 16 float4 chunks)
// Consecutive threads read consecutive float4s -> fully coalesced 128B/warp.
// The scatter side uses red.global.add.v4.f32 (no return value -> REDG path),
// cutting the reduction-op count 4x vs scalar atomicAdd.
__global__ __launch_bounds__(256)
void scatter_add_kernel(const float4* __restrict__ src,
                        const void* __restrict__ idx,
                        float* __restrict__ out,
                        int nrows) {
    long long t = (long long)blockIdx.x * blockDim.x + threadIdx.x;
    long long total = (long long)nrows * 16;
    if (t >= total) return;

    int row = (int)(t >> 4);
    int c   = (int)(t & 15);

    long long seg;
    if (g_idx_is64) {
        seg = __ldg((const long long*)idx + row);
    } else {
        seg = (long long)__ldg((const int*)idx + row);
    }

    float4 v = __ldg(src + t);
    float* dst = out + seg * 64 + (long long)c * 4;

    asm volatile("red.global.add.v4.f32 [%0], {%1, %2, %3, %4};"
                 :: "l"(dst), "f"(v.x), "f"(v.y), "f"(v.z), "f"(v.w)
                 : "memory");
}

extern "C" void kernel_launch(void* const* d_in, const int* in_sizes, int n_in,
                              void* d_out, int out_size) {
    const float4* src = (const float4*)d_in[0];
    const void*   idx = d_in[1];
    float*        out = (float*)d_out;

    int nrows    = in_sizes[1];            // 1,250,000
    long long dim_size = (long long)(out_size / 64);  // 50,000

    // 1) zero the (poisoned) output
    int n4 = out_size / 4;
    zero_out_kernel<<<(n4 + 255) / 256, 256>>>((float4*)d_out, n4);

    // 2) detect index element width (int32 vs int64)
    detect_idx_width_kernel<<<1, 32>>>(idx, dim_size);

    // 3) vectorized scatter-add
    long long total = (long long)nrows * 16;
    int blocks = (int)((total + 255) / 256);
    scatter_add_kernel<<<blocks, 256>>>(src, idx, out, nrows);
}